// round 15
// baseline (speedup 1.0000x reference)
#include <cuda_runtime.h>
#include <cuda_fp16.h>
#include <cstdint>
#include <math.h>

#define BATCH 16
#define CCH   256
#define LSEQ  2048
#define BM    64
#define BN    64
#define NTILES 32
#define NTHREADS 512   // 16 warps

// strides (elements)
#define QSH 264   // Qs halves/row (264/8=33 odd -> ldmatrix conflict-free)
#define KVH 72    // Ks/Vs halves/row (9 odd)
#define PSH 72    // Ps halves/row
#define SSF 68    // Ss floats/row

// byte offsets in dynamic smem
#define QS_B   0                 // 64*264*2 = 33792
#define KS_B   33792             // 2 x (256*72*2 = 36864)
#define KBUF   36864
#define VS_B   (KS_B + 2*KBUF)   // 107520, 2 x 36864
#define VBUF   36864
#define SS_B   (VS_B + 2*VBUF)   // 181248, 64*68*4 = 17408
#define PS_B   (SS_B + 17408)    // 198656, 64*72*2 = 9216
#define MASK_B (PS_B + 9216)     // 207872, 2 x 64 floats
#define LM_B   (MASK_B + 512)    // 208384, 2 x 64 floats
#define DROW_B (LM_B + 512)      // 208896, 64 floats
#define SMEM_BYTES (DROW_B + 256)   // 209152 <= 232448

#define LDSM_X4(r0,r1,r2,r3,addr) \
    asm volatile("ldmatrix.sync.aligned.m8n8.x4.shared.b16 {%0,%1,%2,%3}, [%4];" \
        : "=r"(r0),"=r"(r1),"=r"(r2),"=r"(r3) : "r"(addr))
#define LDSM_X4T(r0,r1,r2,r3,addr) \
    asm volatile("ldmatrix.sync.aligned.m8n8.x4.trans.shared.b16 {%0,%1,%2,%3}, [%4];" \
        : "=r"(r0),"=r"(r1),"=r"(r2),"=r"(r3) : "r"(addr))

__device__ __forceinline__ void hmma(float d[4], uint32_t a0, uint32_t a1, uint32_t a2, uint32_t a3,
                                     uint32_t b0, uint32_t b1) {
    asm volatile(
        "mma.sync.aligned.m16n8k16.row.col.f32.f16.f16.f32 "
        "{%0,%1,%2,%3}, {%4,%5,%6,%7}, {%8,%9}, {%0,%1,%2,%3};\n"
        : "+f"(d[0]), "+f"(d[1]), "+f"(d[2]), "+f"(d[3])
        : "r"(a0), "r"(a1), "r"(a2), "r"(a3), "r"(b0), "r"(b1));
}

__device__ __forceinline__ uint32_t smem_u32(const void* p) {
    uint32_t a;
    asm("{ .reg .u64 t; cvta.to.shared.u64 t, %1; cvt.u32.u64 %0, t; }" : "=r"(a) : "l"(p));
    return a;
}
__device__ __forceinline__ uint32_t pack2(float x, float y) {
    __half2 h = __floats2half2_rn(x, y);
    return *reinterpret_cast<uint32_t*>(&h);
}

__global__ void __launch_bounds__(NTHREADS, 1)
attn_db_kernel(const float* __restrict__ Q, const float* __restrict__ K,
               const float* __restrict__ V, const float* __restrict__ Mask,
               float* __restrict__ Out) {
    extern __shared__ char smem[];
    const uint32_t sb = smem_u32(smem);
    float* Drow = (float*)(smem + DROW_B);

    const int tid = threadIdx.x, w = tid >> 5, lane = tid & 31;
    const int g = lane >> 2, tig = lane & 3;
    const int b = blockIdx.y, l0 = blockIdx.x * BM;

    const float* Qb = Q + (size_t)b * CCH * LSEQ;
    const float* Kb = K + (size_t)b * CCH * LSEQ;
    const float* Vb = V + (size_t)b * CCH * LSEQ;
    const float* Mb = Mask + (size_t)b * LSEQ;

    // ---- stage Q once (fp16, /16): Qs[l][c] ----
    {
        const float s16 = 0.0625f;
        #pragma unroll
        for (int i = 0; i < 8; i++) {
            int idx = i * NTHREADS + tid;   // 0..4095
            int c = idx >> 4, j = idx & 15;
            float4 v = *reinterpret_cast<const float4*>(Qb + (size_t)c * LSEQ + l0 + 4 * j);
            *(__half*)(smem + QS_B + ((4 * j + 0) * QSH + c) * 2) = __float2half_rn(v.x * s16);
            *(__half*)(smem + QS_B + ((4 * j + 1) * QSH + c) * 2) = __float2half_rn(v.y * s16);
            *(__half*)(smem + QS_B + ((4 * j + 2) * QSH + c) * 2) = __float2half_rn(v.z * s16);
            *(__half*)(smem + QS_B + ((4 * j + 3) * QSH + c) * 2) = __float2half_rn(v.w * s16);
        }
    }
    // ---- stage K[0], V[0], mask[0] into buffer 0 ----
    #pragma unroll
    for (int i = 0; i < 8; i++) {
        int idx = i * NTHREADS + tid;
        int c = idx >> 4, j = idx & 15;
        float4 vk = *reinterpret_cast<const float4*>(Kb + (size_t)c * LSEQ + 4 * j);
        float4 vv = *reinterpret_cast<const float4*>(Vb + (size_t)c * LSEQ + 4 * j);
        *reinterpret_cast<uint2*>(smem + KS_B + (c * KVH + 4 * j) * 2) =
            make_uint2(pack2(vk.x, vk.y), pack2(vk.z, vk.w));
        *reinterpret_cast<uint2*>(smem + VS_B + (c * KVH + 4 * j) * 2) =
            make_uint2(pack2(vv.x, vv.y), pack2(vv.z, vv.w));
    }
    if (tid < 64) {
        float mk = Mb[tid];
        ((float*)(smem + MASK_B))[tid] = mk;
        ((float*)(smem + LM_B))[tid] = __logf(mk + 1e-9f);
    }

    // warp tiles: S-GEMM 16x16 (4x4 grid); PV 64 rows x 16 ch
    const int R0 = 16 * (w & 3);
    const int C0 = 16 * (w >> 2);
    const int Cw = 16 * w;

    // ldmatrix lane base addresses (buffer 0; add (t&1)*KBUF/VBUF per tile)
    const uint32_t aQ = sb + QS_B + ((R0 + (lane & 15)) * QSH + 8 * (lane >> 4)) * 2;
    const uint32_t aK = sb + KS_B + (((lane & 7) + 8 * ((lane >> 3) & 1)) * KVH
                                     + C0 + 8 * (lane >> 4)) * 2;
    const uint32_t aP = sb + PS_B + ((lane & 15) * PSH + 8 * (lane >> 4)) * 2;
    const uint32_t aV = sb + VS_B + ((Cw + (lane & 7) + 8 * (lane >> 4)) * KVH
                                     + 8 * ((lane >> 3) & 1)) * 2;

    float O[4][2][4];
    #pragma unroll
    for (int mt = 0; mt < 4; mt++)
        #pragma unroll
        for (int nt = 0; nt < 2; nt++)
            #pragma unroll
            for (int r = 0; r < 4; r++) O[mt][nt][r] = 0.0f;

    const int srow = tid >> 3;
    const int cq   = (tid & 7) * 8;
    float den = 0.0f;

    __syncthreads();

    for (int t = 0; t < NTILES; t++) {
        const int cur = t & 1, nxt = cur ^ 1;

        // ---- S = (Q/16)^T K from Kbuf[cur] ----
        {
            float sacc[2][4];
            #pragma unroll
            for (int nt = 0; nt < 2; nt++)
                #pragma unroll
                for (int r = 0; r < 4; r++) sacc[nt][r] = 0.0f;

            uint32_t qa = aQ, ka = aK + cur * KBUF;
            #pragma unroll
            for (int s = 0; s < 16; s++) {
                uint32_t A0, A1, A2, A3, B0, B1, B2, B3;
                LDSM_X4(A0, A1, A2, A3, qa);
                LDSM_X4T(B0, B1, B2, B3, ka);
                hmma(sacc[0], A0, A1, A2, A3, B0, B1);
                hmma(sacc[1], A0, A1, A2, A3, B2, B3);
                qa += 32;
                ka += 16 * KVH * 2;
            }
            #pragma unroll
            for (int nt = 0; nt < 2; nt++) {
                int col = C0 + 8 * nt + 2 * tig;
                float* p0 = (float*)(smem + SS_B) + (R0 + g) * SSF + col;
                float* p1 = p0 + 8 * SSF;
                p0[0] = sacc[nt][0]; p0[1] = sacc[nt][1];
                p1[0] = sacc[nt][2]; p1[1] = sacc[nt][3];
            }
        }

        // ---- stage K[t+1], V[t+1], mask[t+1] into buffers[nxt] ----
        // (off the critical path: consumed only after the end-of-tile barrier)
        if (t + 1 < NTILES) {
            const int m1 = (t + 1) * BN;
            #pragma unroll
            for (int i = 0; i < 8; i++) {
                int idx = i * NTHREADS + tid;
                int c = idx >> 4, j = idx & 15;
                float4 vk = *reinterpret_cast<const float4*>(Kb + (size_t)c * LSEQ + m1 + 4 * j);
                float4 vv = *reinterpret_cast<const float4*>(Vb + (size_t)c * LSEQ + m1 + 4 * j);
                *reinterpret_cast<uint2*>(smem + KS_B + nxt * KBUF + (c * KVH + 4 * j) * 2) =
                    make_uint2(pack2(vk.x, vk.y), pack2(vk.z, vk.w));
                *reinterpret_cast<uint2*>(smem + VS_B + nxt * VBUF + (c * KVH + 4 * j) * 2) =
                    make_uint2(pack2(vv.x, vv.y), pack2(vv.z, vv.w));
            }
            if (tid < 64) {
                float mk = Mb[m1 + tid];
                ((float*)(smem + MASK_B))[nxt * 64 + tid] = mk;
                ((float*)(smem + LM_B))[nxt * 64 + tid] = __logf(mk + 1e-9f);
            }
        }
        __syncthreads();   // S visible

        // ---- softmax (no max-subtraction; logits bounded ~6) ----
        {
            const float* srcp = (const float*)(smem + SS_B) + srow * SSF + cq;
            float4 s0 = *reinterpret_cast<const float4*>(srcp);
            float4 s1 = *reinterpret_cast<const float4*>(srcp + 4);
            const float* lmp = (const float*)(smem + LM_B) + cur * 64 + cq;
            const float* mp  = (const float*)(smem + MASK_B) + cur * 64 + cq;
            float e0 = __expf(s0.x + lmp[0]), e1 = __expf(s0.y + lmp[1]);
            float e2 = __expf(s0.z + lmp[2]), e3 = __expf(s0.w + lmp[3]);
            float e4 = __expf(s1.x + lmp[4]), e5 = __expf(s1.y + lmp[5]);
            float e6 = __expf(s1.z + lmp[6]), e7 = __expf(s1.w + lmp[7]);
            den += ((e0 + e1) + (e2 + e3)) + ((e4 + e5) + (e6 + e7));
            uint4 pk;
            pk.x = pack2(e0 * mp[0], e1 * mp[1]);
            pk.y = pack2(e2 * mp[2], e3 * mp[3]);
            pk.z = pack2(e4 * mp[4], e5 * mp[5]);
            pk.w = pack2(e6 * mp[6], e7 * mp[7]);
            *reinterpret_cast<uint4*>(smem + PS_B + (srow * PSH + cq) * 2) = pk;
        }
        __syncthreads();   // P visible

        // ---- O += V * P^T from Vbuf[cur] ----
        {
            const uint32_t av = aV + cur * VBUF;
            #pragma unroll
            for (int s = 0; s < 4; s++) {
                uint32_t V0, V1, V2, V3;
                LDSM_X4(V0, V1, V2, V3, av + s * 32);
                #pragma unroll
                for (int mt = 0; mt < 4; mt++) {
                    uint32_t P0, P1, P2, P3;
                    LDSM_X4(P0, P1, P2, P3, aP + mt * (16 * PSH * 2) + s * 32);
                    hmma(O[mt][0], P0, P1, P2, P3, V0, V1);
                    hmma(O[mt][1], P0, P1, P2, P3, V2, V3);
                }
            }
        }
        __syncthreads();   // end of tile: PV done (bufs reusable), staging visible
    }

    // ---- reduce denominators (8 threads per row) ----
    den += __shfl_xor_sync(0xffffffffu, den, 1);
    den += __shfl_xor_sync(0xffffffffu, den, 2);
    den += __shfl_xor_sync(0xffffffffu, den, 4);
    if ((tid & 7) == 0) Drow[srow] = den;
    __syncthreads();

    // ---- epilogue: O/den, transpose via smem scratch, coalesced stores ----
    float* T = (float*)smem + w * 1040;   // 16 ch x 64 l, stride 65
    #pragma unroll
    for (int mt = 0; mt < 4; mt++) {
        float inv0 = 1.0f / Drow[16 * mt + g];
        float inv1 = 1.0f / Drow[16 * mt + 8 + g];
        #pragma unroll
        for (int nt = 0; nt < 2; nt++) {
            int c2 = 8 * nt + 2 * tig;
            T[(c2    ) * 65 + 16 * mt + g    ] = O[mt][nt][0] * inv0;
            T[(c2 + 1) * 65 + 16 * mt + g    ] = O[mt][nt][1] * inv0;
            T[(c2    ) * 65 + 16 * mt + g + 8] = O[mt][nt][2] * inv1;
            T[(c2 + 1) * 65 + 16 * mt + g + 8] = O[mt][nt][3] * inv1;
        }
    }
    __syncwarp();
    float* outw = Out + ((size_t)b * CCH + Cw) * LSEQ + l0;
    #pragma unroll 4
    for (int cl = 0; cl < 16; cl++) {
        float* orow = outw + (size_t)cl * LSEQ;
        orow[lane]      = T[cl * 65 + lane];
        orow[lane + 32] = T[cl * 65 + 32 + lane];
    }
}

extern "C" void kernel_launch(void* const* d_in, const int* in_sizes, int n_in,
                              void* d_out, int out_size) {
    (void)in_sizes; (void)n_in; (void)out_size;
    const float* Q = (const float*)d_in[0];
    const float* K = (const float*)d_in[1];
    const float* V = (const float*)d_in[2];
    const float* M = (const float*)d_in[3];
    float* O = (float*)d_out;

    cudaFuncSetAttribute(attn_db_kernel,
                         cudaFuncAttributeMaxDynamicSharedMemorySize, SMEM_BYTES);
    dim3 grid(LSEQ / BM, BATCH);   // 32 x 16 = 512 CTAs
    attn_db_kernel<<<grid, NTHREADS, SMEM_BYTES>>>(Q, K, V, M, O);
}

// round 16
// speedup vs baseline: 1.1820x; 1.1820x over previous
#include <cuda_runtime.h>
#include <cuda_fp16.h>
#include <cstdint>
#include <math.h>

#define BATCH 16
#define CCH   256
#define LSEQ  2048
#define BM    64
#define BN    64
#define NTILES 32
#define NTHREADS 512   // 16 warps

// strides (elements)
#define QSH 264   // Qs halves/row (33 odd -> ldmatrix conflict-free)
#define KVH 72    // Ks/Vs halves/row (9 odd)
#define PSH 72    // Ps halves/row

// byte offsets in dynamic smem
#define QS_B   0                    // 64*264*2 = 33792
#define KS_B   33792                // 2 x 36864
#define KBUF   36864
#define VS_B   (KS_B + 2*KBUF)      // 107520, 2 x 36864
#define VBUF   36864
#define PS_B   (VS_B + 2*VBUF)      // 181248, 64*72*2 = 9216
#define MASK_B (PS_B + 9216)        // 190464, 2 x 64 floats
#define LM_B   (MASK_B + 512)       // 190976, 2 x 64 floats
#define PART_B (LM_B + 512)         // 191488, 4 x 64 floats
#define DROW_B (PART_B + 1024)      // 192512, 64 floats
#define SMEM_BYTES (DROW_B + 256)   // 192768 <= 232448

#define LDSM_X4(r0,r1,r2,r3,addr) \
    asm volatile("ldmatrix.sync.aligned.m8n8.x4.shared.b16 {%0,%1,%2,%3}, [%4];" \
        : "=r"(r0),"=r"(r1),"=r"(r2),"=r"(r3) : "r"(addr))
#define LDSM_X4T(r0,r1,r2,r3,addr) \
    asm volatile("ldmatrix.sync.aligned.m8n8.x4.trans.shared.b16 {%0,%1,%2,%3}, [%4];" \
        : "=r"(r0),"=r"(r1),"=r"(r2),"=r"(r3) : "r"(addr))

__device__ __forceinline__ void hmma(float d[4], uint32_t a0, uint32_t a1, uint32_t a2, uint32_t a3,
                                     uint32_t b0, uint32_t b1) {
    asm volatile(
        "mma.sync.aligned.m16n8k16.row.col.f32.f16.f16.f32 "
        "{%0,%1,%2,%3}, {%4,%5,%6,%7}, {%8,%9}, {%0,%1,%2,%3};\n"
        : "+f"(d[0]), "+f"(d[1]), "+f"(d[2]), "+f"(d[3])
        : "r"(a0), "r"(a1), "r"(a2), "r"(a3), "r"(b0), "r"(b1));
}

__device__ __forceinline__ uint32_t smem_u32(const void* p) {
    uint32_t a;
    asm("{ .reg .u64 t; cvta.to.shared.u64 t, %1; cvt.u32.u64 %0, t; }" : "=r"(a) : "l"(p));
    return a;
}
__device__ __forceinline__ uint32_t pack2(float x, float y) {
    __half2 h = __floats2half2_rn(x, y);
    return *reinterpret_cast<uint32_t*>(&h);
}

__global__ void __launch_bounds__(NTHREADS, 1)
attn_rs_kernel(const float* __restrict__ Q, const float* __restrict__ K,
               const float* __restrict__ V, const float* __restrict__ Mask,
               float* __restrict__ Out) {
    extern __shared__ char smem[];
    const uint32_t sb = smem_u32(smem);
    float* maskS = (float*)(smem + MASK_B);
    float* lmS   = (float*)(smem + LM_B);
    float* partS = (float*)(smem + PART_B);
    float* Drow  = (float*)(smem + DROW_B);

    const int tid = threadIdx.x, w = tid >> 5, lane = tid & 31;
    const int g = lane >> 2, tig = lane & 3;
    const int b = blockIdx.y, l0 = blockIdx.x * BM;

    const float* Qb = Q + (size_t)b * CCH * LSEQ;
    const float* Kb = K + (size_t)b * CCH * LSEQ;
    const float* Vb = V + (size_t)b * CCH * LSEQ;
    const float* Mb = Mask + (size_t)b * LSEQ;

    // ---- stage Q once (fp16, /16): Qs[l][c] ----
    {
        const float s16 = 0.0625f;
        #pragma unroll
        for (int i = 0; i < 8; i++) {
            int idx = i * NTHREADS + tid;
            int c = idx >> 4, j = idx & 15;
            float4 v = *reinterpret_cast<const float4*>(Qb + (size_t)c * LSEQ + l0 + 4 * j);
            *(__half*)(smem + QS_B + ((4 * j + 0) * QSH + c) * 2) = __float2half_rn(v.x * s16);
            *(__half*)(smem + QS_B + ((4 * j + 1) * QSH + c) * 2) = __float2half_rn(v.y * s16);
            *(__half*)(smem + QS_B + ((4 * j + 2) * QSH + c) * 2) = __float2half_rn(v.z * s16);
            *(__half*)(smem + QS_B + ((4 * j + 3) * QSH + c) * 2) = __float2half_rn(v.w * s16);
        }
    }
    // ---- stage K[0], V[0], mask[0] into buffer 0 ----
    #pragma unroll
    for (int i = 0; i < 8; i++) {
        int idx = i * NTHREADS + tid;
        int c = idx >> 4, j = idx & 15;
        float4 vk = *reinterpret_cast<const float4*>(Kb + (size_t)c * LSEQ + 4 * j);
        float4 vv = *reinterpret_cast<const float4*>(Vb + (size_t)c * LSEQ + 4 * j);
        *reinterpret_cast<uint2*>(smem + KS_B + (c * KVH + 4 * j) * 2) =
            make_uint2(pack2(vk.x, vk.y), pack2(vk.z, vk.w));
        *reinterpret_cast<uint2*>(smem + VS_B + (c * KVH + 4 * j) * 2) =
            make_uint2(pack2(vv.x, vv.y), pack2(vv.z, vv.w));
    }
    if (tid < 64) {
        float mk = Mb[tid];
        maskS[tid] = mk;
        lmS[tid] = __logf(mk + 1e-9f);
    }

    // warp tiles: S-GEMM 16x16 (4x4 grid); PV 64 rows x 16 ch
    const int R0 = 16 * (w & 3);
    const int C0 = 16 * (w >> 2);
    const int Cw = 16 * w;

    const uint32_t aQ = sb + QS_B + ((R0 + (lane & 15)) * QSH + 8 * (lane >> 4)) * 2;
    const uint32_t aK = sb + KS_B + (((lane & 7) + 8 * ((lane >> 3) & 1)) * KVH
                                     + C0 + 8 * (lane >> 4)) * 2;
    const uint32_t aP = sb + PS_B + ((lane & 15) * PSH + 8 * (lane >> 4)) * 2;
    const uint32_t aV = sb + VS_B + ((Cw + (lane & 7) + 8 * (lane >> 4)) * KVH
                                     + 8 * ((lane >> 3) & 1)) * 2;

    float O[4][2][4];
    #pragma unroll
    for (int mt = 0; mt < 4; mt++)
        #pragma unroll
        for (int nt = 0; nt < 2; nt++)
            #pragma unroll
            for (int r = 0; r < 4; r++) O[mt][nt][r] = 0.0f;

    float den0 = 0.0f, den1 = 0.0f;   // rows R0+g, R0+g+8

    __syncthreads();

    #pragma unroll 1
    for (int t = 0; t < NTILES; t++) {
        const int cur = t & 1, nxt = cur ^ 1;
        const int m1 = (t + 1) * BN;
        const bool more = (t + 1 < NTILES);

        // ---- issue K[t+1] prefetch LDGs + mask[t+1] (hidden under S-MMA) ----
        float4 kreg[8];
        float mk1 = 0.0f;
        if (more) {
            #pragma unroll
            for (int i = 0; i < 8; i++) {
                int idx = i * NTHREADS + tid;
                int c = idx >> 4, j = idx & 15;
                kreg[i] = *reinterpret_cast<const float4*>(Kb + (size_t)c * LSEQ + m1 + 4 * j);
            }
            if (tid < 64) mk1 = Mb[m1 + tid];
        }

        // ---- S = (Q/16)^T K from Kbuf[cur] ----
        float sacc[2][4];
        #pragma unroll
        for (int nt = 0; nt < 2; nt++)
            #pragma unroll
            for (int r = 0; r < 4; r++) sacc[nt][r] = 0.0f;
        {
            uint32_t qa = aQ, ka = aK + cur * KBUF;
            #pragma unroll
            for (int s = 0; s < 16; s++) {
                uint32_t A0, A1, A2, A3, B0, B1, B2, B3;
                LDSM_X4(A0, A1, A2, A3, qa);
                LDSM_X4T(B0, B1, B2, B3, ka);
                hmma(sacc[0], A0, A1, A2, A3, B0, B1);
                hmma(sacc[1], A0, A1, A2, A3, B2, B3);
                qa += 32;
                ka += 16 * KVH * 2;
            }
        }

        // ---- softmax on fragments (no max-subtraction; logits bounded ~6) ----
        #pragma unroll
        for (int nt = 0; nt < 2; nt++) {
            int c = C0 + 8 * nt + 2 * tig;
            float2 lm01 = *reinterpret_cast<const float2*>(lmS + cur * 64 + c);
            float2 m01  = *reinterpret_cast<const float2*>(maskS + cur * 64 + c);
            float e00 = __expf(sacc[nt][0] + lm01.x);
            float e01 = __expf(sacc[nt][1] + lm01.y);
            float e10 = __expf(sacc[nt][2] + lm01.x);
            float e11 = __expf(sacc[nt][3] + lm01.y);
            den0 += e00 + e01;
            den1 += e10 + e11;
            *reinterpret_cast<uint32_t*>(smem + PS_B + ((R0 + g) * PSH + c) * 2) =
                pack2(e00 * m01.x, e01 * m01.y);
            *reinterpret_cast<uint32_t*>(smem + PS_B + ((R0 + g + 8) * PSH + c) * 2) =
                pack2(e10 * m01.x, e11 * m01.y);
        }

        // ---- STS K[t+1] (data long since arrived) + mask[t+1] ----
        if (more) {
            #pragma unroll
            for (int i = 0; i < 8; i++) {
                int idx = i * NTHREADS + tid;
                int c = idx >> 4, j = idx & 15;
                *reinterpret_cast<uint2*>(smem + KS_B + nxt * KBUF + (c * KVH + 4 * j) * 2) =
                    make_uint2(pack2(kreg[i].x, kreg[i].y), pack2(kreg[i].z, kreg[i].w));
            }
            if (tid < 64) {
                maskS[nxt * 64 + tid] = mk1;
                lmS[nxt * 64 + tid] = __logf(mk1 + 1e-9f);
            }
        }
        __syncthreads();   // P + Kbuf[nxt] + mask[nxt] visible

        // ---- issue V[t+1] prefetch LDGs (hidden under PV) ----
        float4 vreg[8];
        if (more) {
            #pragma unroll
            for (int i = 0; i < 8; i++) {
                int idx = i * NTHREADS + tid;
                int c = idx >> 4, j = idx & 15;
                vreg[i] = *reinterpret_cast<const float4*>(Vb + (size_t)c * LSEQ + m1 + 4 * j);
            }
        }

        // ---- O += V * P^T from Vbuf[cur] ----
        {
            const uint32_t av = aV + cur * VBUF;
            #pragma unroll
            for (int s = 0; s < 4; s++) {
                uint32_t V0, V1, V2, V3;
                LDSM_X4(V0, V1, V2, V3, av + s * 32);
                #pragma unroll
                for (int mt = 0; mt < 4; mt++) {
                    uint32_t P0, P1, P2, P3;
                    LDSM_X4(P0, P1, P2, P3, aP + mt * (16 * PSH * 2) + s * 32);
                    hmma(O[mt][0], P0, P1, P2, P3, V0, V1);
                    hmma(O[mt][1], P0, P1, P2, P3, V2, V3);
                }
            }
        }

        // ---- STS V[t+1] ----
        if (more) {
            #pragma unroll
            for (int i = 0; i < 8; i++) {
                int idx = i * NTHREADS + tid;
                int c = idx >> 4, j = idx & 15;
                *reinterpret_cast<uint2*>(smem + VS_B + nxt * VBUF + (c * KVH + 4 * j) * 2) =
                    make_uint2(pack2(vreg[i].x, vreg[i].y), pack2(vreg[i].z, vreg[i].w));
            }
        }
        __syncthreads();   // end of tile: PV reads done, Vbuf[nxt] visible
    }

    // ---- denominator reduction: shfl over tig, then 4 C0-groups via smem ----
    den0 += __shfl_xor_sync(0xffffffffu, den0, 1);
    den0 += __shfl_xor_sync(0xffffffffu, den0, 2);
    den1 += __shfl_xor_sync(0xffffffffu, den1, 1);
    den1 += __shfl_xor_sync(0xffffffffu, den1, 2);
    if (tig == 0) {
        partS[(w >> 2) * 64 + R0 + g]     = den0;
        partS[(w >> 2) * 64 + R0 + g + 8] = den1;
    }
    __syncthreads();
    if (tid < 64)
        Drow[tid] = partS[tid] + partS[64 + tid] + partS[128 + tid] + partS[192 + tid];
    __syncthreads();

    // ---- epilogue: O/den, transpose via smem scratch (reuse Q/K area), coalesced stores ----
    float* T = (float*)smem + w * 1040;   // 16 ch x 64 l, stride 65
    #pragma unroll
    for (int mt = 0; mt < 4; mt++) {
        float inv0 = 1.0f / Drow[16 * mt + g];
        float inv1 = 1.0f / Drow[16 * mt + 8 + g];
        #pragma unroll
        for (int nt = 0; nt < 2; nt++) {
            int c2 = 8 * nt + 2 * tig;
            T[(c2    ) * 65 + 16 * mt + g    ] = O[mt][nt][0] * inv0;
            T[(c2 + 1) * 65 + 16 * mt + g    ] = O[mt][nt][1] * inv0;
            T[(c2    ) * 65 + 16 * mt + g + 8] = O[mt][nt][2] * inv1;
            T[(c2 + 1) * 65 + 16 * mt + g + 8] = O[mt][nt][3] * inv1;
        }
    }
    __syncwarp();
    float* outw = Out + ((size_t)b * CCH + Cw) * LSEQ + l0;
    #pragma unroll 4
    for (int cl = 0; cl < 16; cl++) {
        float* orow = outw + (size_t)cl * LSEQ;
        orow[lane]      = T[cl * 65 + lane];
        orow[lane + 32] = T[cl * 65 + 32 + lane];
    }
}

extern "C" void kernel_launch(void* const* d_in, const int* in_sizes, int n_in,
                              void* d_out, int out_size) {
    (void)in_sizes; (void)n_in; (void)out_size;
    const float* Q = (const float*)d_in[0];
    const float* K = (const float*)d_in[1];
    const float* V = (const float*)d_in[2];
    const float* M = (const float*)d_in[3];
    float* O = (float*)d_out;

    cudaFuncSetAttribute(attn_rs_kernel,
                         cudaFuncAttributeMaxDynamicSharedMemorySize, SMEM_BYTES);
    dim3 grid(LSEQ / BM, BATCH);   // 32 x 16 = 512 CTAs
    attn_rs_kernel<<<grid, NTHREADS, SMEM_BYTES>>>(Q, K, V, M, O);
}